// round 5
// baseline (speedup 1.0000x reference)
#include <cuda_runtime.h>
#include <math.h>

#define NCHUNK 256
#define LC 512
#define HID 256
#define MD 283
#define DEPTH 7
#define LTOT (NCHUNK * LC)   // 131072 positions total

#define PITCH 136            // floats per A-row; 136 % 32 == 8 -> conflict-free frags
#define ASMEM (48 * PITCH)   // 6528 words
#define BSMEM 6144
#define CONV_SMEM_BYTES ((ASMEM + BSMEM) * 4)

// Ping-pong activation buffers: (chunk, channel, pos) layout, fp32.
__device__ float g_bufA[NCHUNK * HID * LC];
__device__ float g_bufB[NCHUNK * HID * LC];
// Tower weights pre-permuted into m16n8k8 tf32 B-fragment layout:
// [layer][kc16(16)][ohalf(2)][kstep(6)][ntile(16)][lane(32)][reg(2)]
__device__ unsigned g_wF[DEPTH * 16 * 2 * 6144];
// Transposed proj weights: [m][h]
__device__ float g_wpT[MD * HID];

// ---------------------------------------------------------------------------
// Weight prep
// ---------------------------------------------------------------------------
__global__ void prep_kernel(const float* __restrict__ tower_w,
                            const float* __restrict__ w_proj) {
    int i = blockIdx.x * blockDim.x + threadIdx.x;
    if (i < DEPTH * 16 * 2 * 6144) {
        int local = i % 6144;
        int blk = i / 6144;
        int reg = local & 1;
        int ln = (local >> 1) & 31;
        int nt = (local >> 6) & 15;
        int ks = local >> 10;             // 0..5
        int ohalf = blk & 1;
        int kc16 = (blk >> 1) & 15;
        int layer = blk >> 5;
        int t = ks >> 1;
        int ic = kc16 * 16 + (ln & 3) + 4 * reg + 8 * (ks & 1);
        int oc = ohalf * 128 + nt * 8 + (ln >> 2);
        float v = tower_w[(((layer * HID + oc) * HID) + ic) * 3 + t];
        unsigned tv; asm("cvt.rna.tf32.f32 %0, %1;" : "=r"(tv) : "f"(v));
        g_wF[i] = tv;
    }
    if (i < MD * HID) {
        int h = i & 255;
        int m = i >> 8;
        g_wpT[i] = w_proj[h * MD + m];
    }
}

// ---------------------------------------------------------------------------
// Projection: GEMM M=131072 (pos), N=256 (h), K=283. fp32 SIMT 8x8/thread.
// ---------------------------------------------------------------------------
__global__ __launch_bounds__(256, 2)
void proj_kernel(const float* __restrict__ x) {
    int m0 = blockIdx.x * 128;
    int hb = blockIdx.y * 128;
    __shared__ float As[128][16];
    __shared__ float Bs[16][128];
    int tid = threadIdx.x;
    int tx = tid & 15, ty = tid >> 4;
    float acc[8][8];
#pragma unroll
    for (int i = 0; i < 8; i++)
#pragma unroll
        for (int j = 0; j < 8; j++) acc[i][j] = 0.f;

    for (int kc = 0; kc < 288; kc += 16) {
        __syncthreads();
#pragma unroll
        for (int r = 0; r < 8; r++) {
            int e = r * 256 + tid;
            int p = e >> 4, k = e & 15;
            As[p][k] = (kc + k < MD) ? x[(size_t)(m0 + p) * MD + kc + k] : 0.f;
        }
#pragma unroll
        for (int r = 0; r < 8; r++) {
            int e = r * 256 + tid;
            int k = e >> 7, h = e & 127;
            Bs[k][h] = (kc + k < MD) ? g_wpT[(kc + k) * HID + hb + h] : 0.f;
        }
        __syncthreads();
#pragma unroll
        for (int k = 0; k < 16; k++) {
            float a[8], b[8];
#pragma unroll
            for (int i = 0; i < 8; i++) a[i] = As[ty * 8 + i][k];
            float4 b0 = *(const float4*)&Bs[k][tx * 8];
            float4 b1 = *(const float4*)&Bs[k][tx * 8 + 4];
            b[0] = b0.x; b[1] = b0.y; b[2] = b0.z; b[3] = b0.w;
            b[4] = b1.x; b[5] = b1.y; b[6] = b1.z; b[7] = b1.w;
#pragma unroll
            for (int i = 0; i < 8; i++)
#pragma unroll
                for (int j = 0; j < 8; j++) acc[i][j] = fmaf(a[i], b[j], acc[i][j]);
        }
    }
    int n = m0 >> 9;
    int lbase = (m0 & 511) + ty * 8;
#pragma unroll
    for (int j = 0; j < 8; j++) {
        int oc = hb + tx * 8 + j;
        float* o = g_bufA + ((size_t)n * HID + oc) * LC + lbase;
        *(float4*)o = make_float4(acc[0][j], acc[1][j], acc[2][j], acc[3][j]);
        *(float4*)(o + 4) = make_float4(acc[4][j], acc[5][j], acc[6][j], acc[7][j]);
    }
}

// ---------------------------------------------------------------------------
// Dilated conv layer via mma.sync m16n8k8 tf32.
// CTA tile 128 pos x 128 oc; 8 warps 2(m) x 4(n); warp tile 64 pos x 32 oc.
// A staged in NATURAL [row=(t,ic)][pos] layout (coalesced float2 LDG + STS.64),
// fragments gathered in mainloop via conflict-free LDS.32 (pitch 136).
// B copied from pre-permuted g_wF fragment layout (coalesced uint4).
// ---------------------------------------------------------------------------
__global__ __launch_bounds__(256, 2)
void conv_kernel(int layer, int d, int srcB, const float* __restrict__ bias) {
    extern __shared__ unsigned sm[];
    unsigned* smA = sm;            // ASMEM words
    unsigned* smB = sm + ASMEM;    // BSMEM words

    const float* in = srcB ? g_bufB : g_bufA;
    float* out = srcB ? g_bufA : g_bufB;
    int l0 = blockIdx.x * 128;
    int ocb = blockIdx.y * 128;
    int n = blockIdx.z;

    int tid = threadIdx.x;
    int lane = tid & 31;
    int warp = tid >> 5;
    int wm = warp & 1;
    int wn = warp >> 1;
    int tig = lane & 3;
    int grp = lane >> 2;

    const float* inb = in + (size_t)n * HID * LC;

    float acc[4][4][4];
#pragma unroll
    for (int i = 0; i < 4; i++)
#pragma unroll
        for (int j = 0; j < 4; j++)
#pragma unroll
            for (int c = 0; c < 4; c++) acc[i][j][c] = 0.f;

    for (int kc16 = 0; kc16 < 16; kc16++) {
        int kc = kc16 * 16;
        __syncthreads();
        // Stage A: 48 rows x 128 pos, coalesced float2 loads, tf32 convert
#pragma unroll
        for (int r = 0; r < 12; r++) {
            int e = r * 256 + tid;          // 0..3071
            int row = e >> 6;               // 0..47 : t*16 + kk
            int p = (e & 63) << 1;          // 0..126 even
            int t = row >> 4;
            int pos = l0 + p + (t - 1) * d; // even (d even, l0 mult 128)
            float2 v = make_float2(0.f, 0.f);
            if ((unsigned)pos < LC)
                v = *(const float2*)(inb + (size_t)(kc + (row & 15)) * LC + pos);
            unsigned u0, u1;
            asm("cvt.rna.tf32.f32 %0, %1;" : "=r"(u0) : "f"(v.x));
            asm("cvt.rna.tf32.f32 %0, %1;" : "=r"(u1) : "f"(v.y));
            *(uint2*)(smA + row * PITCH + p) = make_uint2(u0, u1);
        }
        // Stage B: straight copy of pre-permuted fragment block
        const uint4* src = (const uint4*)(g_wF +
            (((size_t)layer * 16 + kc16) * 2 + blockIdx.y) * 6144);
#pragma unroll
        for (int r = 0; r < 6; r++)
            ((uint4*)smB)[r * 256 + tid] = src[r * 256 + tid];
        __syncthreads();

#pragma unroll
        for (int ks = 0; ks < 6; ks++) {
            int rb = (ks >> 1) * 16 + (ks & 1) * 8;
            const unsigned* ar0 = smA + (rb + tig) * PITCH + grp + wm * 64;
            const unsigned* ar1 = smA + (rb + tig + 4) * PITCH + grp + wm * 64;
            unsigned a[4][4], b[4][2];
#pragma unroll
            for (int i = 0; i < 4; i++) {
                a[i][0] = ar0[i * 16];
                a[i][1] = ar0[i * 16 + 8];
                a[i][2] = ar1[i * 16];
                a[i][3] = ar1[i * 16 + 8];
            }
#pragma unroll
            for (int j = 0; j < 4; j++) {
                uint2 bv = ((const uint2*)smB)[(ks * 16 + wn * 4 + j) * 32 + lane];
                b[j][0] = bv.x; b[j][1] = bv.y;
            }
#pragma unroll
            for (int i = 0; i < 4; i++)
#pragma unroll
                for (int j = 0; j < 4; j++) {
                    asm volatile(
                        "mma.sync.aligned.m16n8k8.row.col.f32.tf32.tf32.f32 "
                        "{%0,%1,%2,%3}, {%4,%5,%6,%7}, {%8,%9}, {%0,%1,%2,%3};"
                        : "+f"(acc[i][j][0]), "+f"(acc[i][j][1]),
                          "+f"(acc[i][j][2]), "+f"(acc[i][j][3])
                        : "r"(a[i][0]), "r"(a[i][1]), "r"(a[i][2]), "r"(a[i][3]),
                          "r"(b[j][0]), "r"(b[j][1]));
                }
        }
    }

    // Epilogue: bias + gelu(c)+c
#pragma unroll
    for (int j = 0; j < 4; j++) {
        int oc0 = ocb + wn * 32 + j * 8 + tig * 2;
        float b0 = bias[oc0], b1 = bias[oc0 + 1];
#pragma unroll
        for (int i = 0; i < 4; i++) {
            int posb = l0 + wm * 64 + i * 16 + grp;
#pragma unroll
            for (int cr = 0; cr < 4; cr++) {
                int pos = posb + ((cr & 2) ? 8 : 0);
                int oc = oc0 + (cr & 1);
                float c = acc[i][j][cr] + ((cr & 1) ? b1 : b0);
                float g = 0.5f * c * (1.f + erff(c * 0.70710678118654752f)) + c;
                out[((size_t)n * HID + oc) * LC + pos] = g;
            }
        }
    }
}

// ---------------------------------------------------------------------------
// Heads: profile conv (K=20, pad 9/10) + mean-pool + atpm + mask.
// ---------------------------------------------------------------------------
__global__ __launch_bounds__(256)
void heads_kernel(const float* __restrict__ w_prof, const float* __restrict__ b_prof,
                  const float* __restrict__ w_atpm, const float* __restrict__ b_atpm,
                  const int* __restrict__ npq, float* __restrict__ out) {
    const float* in = g_bufB;
    int n = blockIdx.x;
    int tid = threadIdx.x;

    __shared__ float wp[HID * 20];
    __shared__ float wa[HID];
    __shared__ float row[LC];
    __shared__ float partial[256];

    for (int i = tid; i < HID * 20; i += 256) wp[i] = w_prof[i];
    wa[tid] = w_atpm[tid];

    float p0 = 0.f, p1 = 0.f, ap = 0.f;
    const float* base = in + (size_t)n * HID * LC;

    for (int ic = 0; ic < HID; ic++) {
        __syncthreads();
        row[tid] = base[ic * LC + tid];
        row[tid + 256] = base[ic * LC + tid + 256];
        __syncthreads();
        const float* wpr = &wp[ic * 20];
        float wv = wa[ic];
#pragma unroll
        for (int k = 0; k < 20; k++) {
            float w = wpr[k];
            int pos = tid + k - 9;
            if (pos >= 0 && pos < LC) p0 = fmaf(row[pos], w, p0);
            int pos2 = tid + 256 + k - 9;
            if (pos2 < LC) p1 = fmaf(row[pos2], w, p1);
        }
        ap = fmaf(wv, row[tid] + row[tid + 256], ap);
    }

    float bp = b_prof[0];
    out[256 + (size_t)n * LC + tid] = p0 + bp;
    out[256 + (size_t)n * LC + tid + 256] = p1 + bp;

    partial[tid] = ap;
    __syncthreads();
    for (int s = 128; s > 0; s >>= 1) {
        if (tid < s) partial[tid] += partial[tid + s];
        __syncthreads();
    }
    if (tid == 0) {
        float atpm = partial[0] * (1.f / 512.f) + b_atpm[0];
        int b = n >> 7, p = n & 127;
        int np;
        int q0 = npq[0], q1 = npq[1];
        if (q1 == 0) {
            int q2 = npq[2], q3 = npq[3];
            if (q3 == 0 && q2 >= 0 && q2 < 128 && q0 >= 0 && q0 < 128) {
                np = (b == 0) ? q0 : q2;   // little-endian int64 [n0, n1]
            } else {
                np = (b == 0) ? q0 : q1;
            }
        } else {
            np = (b == 0) ? q0 : q1;
        }
        out[n] = (p < np) ? atpm : 0.f;
    }
}

// ---------------------------------------------------------------------------
extern "C" void kernel_launch(void* const* d_in, const int* in_sizes, int n_in,
                              void* d_out, int out_size) {
    const float* x       = (const float*)d_in[0];
    const float* w_proj  = (const float*)d_in[1];
    const float* tower_w = (const float*)d_in[2];
    const float* tower_b = (const float*)d_in[3];
    const float* w_prof  = (const float*)d_in[4];
    const float* b_prof  = (const float*)d_in[5];
    const float* w_atpm  = (const float*)d_in[6];
    const float* b_atpm  = (const float*)d_in[7];
    const int*   n_peaks = (const int*)d_in[8];
    float* out = (float*)d_out;

    cudaFuncSetAttribute(conv_kernel,
                         cudaFuncAttributeMaxDynamicSharedMemorySize,
                         CONV_SMEM_BYTES);

    prep_kernel<<<(DEPTH * 16 * 2 * 6144 + 255) / 256, 256>>>(tower_w, w_proj);
    proj_kernel<<<dim3(LTOT / 128, HID / 128), 256>>>(x);
    for (int i = 0; i < DEPTH; i++) {
        conv_kernel<<<dim3(LC / 128, HID / 128, NCHUNK), 256, CONV_SMEM_BYTES>>>(
            i, 2 << i, i & 1, tower_b + i * HID);
    }
    heads_kernel<<<NCHUNK, 256>>>(w_prof, b_prof, w_atpm, b_atpm, n_peaks, out);
}

// round 7
// speedup vs baseline: 1.0686x; 1.0686x over previous
#include <cuda_runtime.h>
#include <math.h>
#include <stdint.h>

#define NCHUNK 256
#define LC 512
#define HID 256
#define MD 283
#define DEPTH 7
#define LTOT (NCHUNK * LC)

#define PITCH 136            // floats per A-row; 136 % 32 == 8 -> conflict-free frags
#define ASZ (48 * PITCH)     // 6528 words per A buffer
#define BSZ 12288            // words per B buffer (6 ks x 32 ntile x 32 lane x 2)
#define CONV_SMEM (2 * (ASZ + BSZ) * 4)   // 150528 bytes

// Ping-pong activation buffers [n][ch][pos]; intermediate layers hold
// tf32-rounded fp32 (so staging is a pure copy), final layer holds full fp32.
__device__ float g_bufA[NCHUNK * HID * LC];
__device__ float g_bufB[NCHUNK * HID * LC];
// Tower weights pre-permuted into m16n8k8 tf32 B-fragment layout:
// [layer][kc16(16)][kstep(6)][ntile(32)][lane(32)][reg(2)]  (tf32 bits as float)
__device__ float g_wF2[DEPTH * 16 * BSZ];
// Transposed proj weights: [m][h]
__device__ float g_wpT[MD * HID];

// ---------------------------------------------------------------------------
// Weight prep
// ---------------------------------------------------------------------------
__global__ void prep_kernel(const float* __restrict__ tower_w,
                            const float* __restrict__ w_proj) {
    int i = blockIdx.x * blockDim.x + threadIdx.x;
    if (i < DEPTH * 16 * BSZ) {
        int local = i % BSZ;
        int blk = i / BSZ;
        int kc16 = blk & 15;
        int layer = blk >> 4;
        int reg = local & 1;
        int ln = (local >> 1) & 31;
        int nt = (local >> 6) & 31;
        int ks = local >> 11;               // 0..5
        int t = ks >> 1;
        int ic = kc16 * 16 + (ln & 3) + 4 * reg + 8 * (ks & 1);
        int oc = nt * 8 + (ln >> 2);
        float v = tower_w[(((layer * HID + oc) * HID) + ic) * 3 + t];
        unsigned tv; asm("cvt.rna.tf32.f32 %0, %1;" : "=r"(tv) : "f"(v));
        g_wF2[i] = __uint_as_float(tv);
    }
    if (i < MD * HID) {
        int h = i & 255;
        int m = i >> 8;
        g_wpT[i] = w_proj[h * MD + m];
    }
}

// ---------------------------------------------------------------------------
// Projection: GEMM M=131072 (pos), N=256 (h), K=283. fp32 SIMT 8x8/thread.
// Output stored tf32-rounded (conv layers consume it directly).
// ---------------------------------------------------------------------------
__global__ __launch_bounds__(256, 2)
void proj_kernel(const float* __restrict__ x) {
    int m0 = blockIdx.x * 128;
    int hb = blockIdx.y * 128;
    __shared__ float As[128][16];
    __shared__ float Bs[16][128];
    int tid = threadIdx.x;
    int tx = tid & 15, ty = tid >> 4;
    float acc[8][8];
#pragma unroll
    for (int i = 0; i < 8; i++)
#pragma unroll
        for (int j = 0; j < 8; j++) acc[i][j] = 0.f;

    for (int kc = 0; kc < 288; kc += 16) {
        __syncthreads();
#pragma unroll
        for (int r = 0; r < 8; r++) {
            int e = r * 256 + tid;
            int p = e >> 4, k = e & 15;
            As[p][k] = (kc + k < MD) ? x[(size_t)(m0 + p) * MD + kc + k] : 0.f;
        }
#pragma unroll
        for (int r = 0; r < 8; r++) {
            int e = r * 256 + tid;
            int k = e >> 7, h = e & 127;
            Bs[k][h] = (kc + k < MD) ? g_wpT[(kc + k) * HID + hb + h] : 0.f;
        }
        __syncthreads();
#pragma unroll
        for (int k = 0; k < 16; k++) {
            float a[8], b[8];
#pragma unroll
            for (int i = 0; i < 8; i++) a[i] = As[ty * 8 + i][k];
            float4 b0 = *(const float4*)&Bs[k][tx * 8];
            float4 b1 = *(const float4*)&Bs[k][tx * 8 + 4];
            b[0] = b0.x; b[1] = b0.y; b[2] = b0.z; b[3] = b0.w;
            b[4] = b1.x; b[5] = b1.y; b[6] = b1.z; b[7] = b1.w;
#pragma unroll
            for (int i = 0; i < 8; i++)
#pragma unroll
                for (int j = 0; j < 8; j++) acc[i][j] = fmaf(a[i], b[j], acc[i][j]);
        }
    }
    int n = m0 >> 9;
    int lbase = (m0 & 511) + ty * 8;
#pragma unroll
    for (int j = 0; j < 8; j++) {
        int oc = hb + tx * 8 + j;
        float v[8];
#pragma unroll
        for (int i = 0; i < 8; i++) {
            unsigned tv;
            asm("cvt.rna.tf32.f32 %0, %1;" : "=r"(tv) : "f"(acc[i][j]));
            v[i] = __uint_as_float(tv);
        }
        float* o = g_bufA + ((size_t)n * HID + oc) * LC + lbase;
        *(float4*)o = make_float4(v[0], v[1], v[2], v[3]);
        *(float4*)(o + 4) = make_float4(v[4], v[5], v[6], v[7]);
    }
}

// ---------------------------------------------------------------------------
// Stage one K-chunk: A (activations, natural layout, 8B cp.async with tap
// shift + zero fill) and B (pre-permuted fragments, 16B cp.async).
// ---------------------------------------------------------------------------
__device__ __forceinline__ void stage_chunk(const float* __restrict__ inb,
                                            int layer, int kc16, int l0, int d,
                                            uint32_t sA, uint32_t sB, int tid) {
    int kc = kc16 * 16;
#pragma unroll
    for (int r = 0; r < 12; r++) {
        int idx = r * 256 + tid;        // 0..3071
        int row = idx >> 6;             // 0..47 : t*16 + kk
        int c8 = idx & 63;              // 8B chunk within row
        int tt = row >> 4;
        int gpos = l0 + c8 * 2 + (tt - 1) * d;
        int ok = ((unsigned)gpos < (unsigned)LC) ? 8 : 0;
        const float* gs = inb + (size_t)(kc + (row & 15)) * LC + (ok ? gpos : 0);
        asm volatile("cp.async.ca.shared.global [%0], [%1], 8, %2;"
                     :: "r"(sA + (unsigned)(row * PITCH + c8 * 2) * 4u),
                        "l"(__cvta_generic_to_global(gs)), "r"(ok));
    }
    const float* ws = g_wF2 + ((size_t)layer * 16 + kc16) * BSZ;
#pragma unroll
    for (int r = 0; r < 12; r++) {
        int idx = r * 256 + tid;        // 0..3071 x 16B
        asm volatile("cp.async.cg.shared.global [%0], [%1], 16, 16;"
                     :: "r"(sB + (unsigned)idx * 16u),
                        "l"(__cvta_generic_to_global(ws + idx * 4)));
    }
    asm volatile("cp.async.commit_group;" ::: "memory");
}

// ---------------------------------------------------------------------------
// Dilated conv layer via mma.sync m16n8k8 tf32.
// CTA tile 128 pos x 256 oc; 8 warps 2(m) x 4(n); warp tile 64 pos x 64 oc.
// Double-buffered cp.async K-chunk pipeline; activations pre-tf32 in gmem.
// ---------------------------------------------------------------------------
__global__ __launch_bounds__(256, 1)
void conv_kernel(int layer, int d, int srcB, int last,
                 const float* __restrict__ bias) {
    extern __shared__ float sm[];
    float* Ab[2] = {sm, sm + ASZ};
    float* Bb[2] = {sm + 2 * ASZ, sm + 2 * ASZ + BSZ};
    uint32_t sbase = (uint32_t)__cvta_generic_to_shared(sm);
    uint32_t sAa[2] = {sbase, sbase + ASZ * 4};
    uint32_t sBa[2] = {sbase + 2 * ASZ * 4, sbase + (2 * ASZ + BSZ) * 4};

    const float* in = srcB ? g_bufB : g_bufA;
    float* out = srcB ? g_bufA : g_bufB;
    int l0 = blockIdx.x * 128;
    int n = blockIdx.y;

    int tid = threadIdx.x;
    int lane = tid & 31;
    int warp = tid >> 5;
    int wm = warp & 1;
    int wn = warp >> 1;
    int tig = lane & 3;
    int grp = lane >> 2;

    const float* inb = in + (size_t)n * HID * LC;

    float acc[4][8][4];
#pragma unroll
    for (int i = 0; i < 4; i++)
#pragma unroll
        for (int j = 0; j < 8; j++)
#pragma unroll
            for (int c = 0; c < 4; c++) acc[i][j][c] = 0.f;

    stage_chunk(inb, layer, 0, l0, d, sAa[0], sBa[0], tid);

    for (int c = 0; c < 16; c++) {
        if (c < 15) {
            stage_chunk(inb, layer, c + 1, l0, d, sAa[(c + 1) & 1],
                        sBa[(c + 1) & 1], tid);
            asm volatile("cp.async.wait_group 1;" ::: "memory");
        } else {
            asm volatile("cp.async.wait_group 0;" ::: "memory");
        }
        __syncthreads();
        const float* Abuf = Ab[c & 1];
        const float* Bbuf = Bb[c & 1];
#pragma unroll
        for (int ks = 0; ks < 6; ks++) {
            int rb = (ks >> 1) * 16 + (ks & 1) * 8;
            const float* ar0 = Abuf + (rb + tig) * PITCH + grp + wm * 64;
            const float* ar1 = Abuf + (rb + tig + 4) * PITCH + grp + wm * 64;
            unsigned a[4][4], b[8][2];
#pragma unroll
            for (int i = 0; i < 4; i++) {
                a[i][0] = __float_as_uint(ar0[i * 16]);
                a[i][1] = __float_as_uint(ar0[i * 16 + 8]);
                a[i][2] = __float_as_uint(ar1[i * 16]);
                a[i][3] = __float_as_uint(ar1[i * 16 + 8]);
            }
#pragma unroll
            for (int j = 0; j < 8; j++) {
                uint2 bv = ((const uint2*)Bbuf)[(ks * 32 + wn * 8 + j) * 32 + lane];
                b[j][0] = bv.x; b[j][1] = bv.y;
            }
#pragma unroll
            for (int i = 0; i < 4; i++)
#pragma unroll
                for (int j = 0; j < 8; j++) {
                    asm volatile(
                        "mma.sync.aligned.m16n8k8.row.col.f32.tf32.tf32.f32 "
                        "{%0,%1,%2,%3}, {%4,%5,%6,%7}, {%8,%9}, {%0,%1,%2,%3};"
                        : "+f"(acc[i][j][0]), "+f"(acc[i][j][1]),
                          "+f"(acc[i][j][2]), "+f"(acc[i][j][3])
                        : "r"(a[i][0]), "r"(a[i][1]), "r"(a[i][2]), "r"(a[i][3]),
                          "r"(b[j][0]), "r"(b[j][1]));
                }
        }
        __syncthreads();
    }

    // Epilogue: bias + gelu(c)+c; intermediate layers store tf32-rounded.
#pragma unroll
    for (int j = 0; j < 8; j++) {
        int oc0 = wn * 64 + j * 8 + tig * 2;
        float b0 = bias[oc0], b1 = bias[oc0 + 1];
#pragma unroll
        for (int i = 0; i < 4; i++) {
            int posb = l0 + wm * 64 + i * 16 + grp;
#pragma unroll
            for (int cr = 0; cr < 4; cr++) {
                int pos = posb + ((cr & 2) ? 8 : 0);
                int oc = oc0 + (cr & 1);
                float cc = acc[i][j][cr] + ((cr & 1) ? b1 : b0);
                float g = 0.5f * cc * (1.f + erff(cc * 0.70710678118654752f)) + cc;
                if (!last) {
                    unsigned tv;
                    asm("cvt.rna.tf32.f32 %0, %1;" : "=r"(tv) : "f"(g));
                    g = __uint_as_float(tv);
                }
                out[((size_t)n * HID + oc) * LC + pos] = g;
            }
        }
    }
}

// ---------------------------------------------------------------------------
// Heads: profile conv (K=20, pad 9/10) + mean-pool + atpm + mask.
// ---------------------------------------------------------------------------
__global__ __launch_bounds__(256)
void heads_kernel(const float* __restrict__ w_prof, const float* __restrict__ b_prof,
                  const float* __restrict__ w_atpm, const float* __restrict__ b_atpm,
                  const int* __restrict__ npq, float* __restrict__ out) {
    const float* in = g_bufB;   // DEPTH=7: final layer (i=6, srcB=0) wrote B
    int n = blockIdx.x;
    int tid = threadIdx.x;

    __shared__ float wp[HID * 20];
    __shared__ float wa[HID];
    __shared__ float row[LC];
    __shared__ float partial[256];

    for (int i = tid; i < HID * 20; i += 256) wp[i] = w_prof[i];
    wa[tid] = w_atpm[tid];

    float p0 = 0.f, p1 = 0.f, ap = 0.f;
    const float* base = in + (size_t)n * HID * LC;

    for (int ic = 0; ic < HID; ic++) {
        __syncthreads();
        row[tid] = base[ic * LC + tid];
        row[tid + 256] = base[ic * LC + tid + 256];
        __syncthreads();
        const float* wpr = &wp[ic * 20];
        float wv = wa[ic];
#pragma unroll
        for (int k = 0; k < 20; k++) {
            float w = wpr[k];
            int pos = tid + k - 9;
            if (pos >= 0 && pos < LC) p0 = fmaf(row[pos], w, p0);
            int pos2 = tid + 256 + k - 9;
            if (pos2 < LC) p1 = fmaf(row[pos2], w, p1);
        }
        ap = fmaf(wv, row[tid] + row[tid + 256], ap);
    }

    float bp = b_prof[0];
    out[256 + (size_t)n * LC + tid] = p0 + bp;
    out[256 + (size_t)n * LC + tid + 256] = p1 + bp;

    partial[tid] = ap;
    __syncthreads();
    for (int s = 128; s > 0; s >>= 1) {
        if (tid < s) partial[tid] += partial[tid + s];
        __syncthreads();
    }
    if (tid == 0) {
        float atpm = partial[0] * (1.f / 512.f) + b_atpm[0];
        int b = n >> 7, p = n & 127;
        int np;
        int q0 = npq[0], q1 = npq[1];
        if (q1 == 0) {
            int q2 = npq[2], q3 = npq[3];
            if (q3 == 0 && q2 >= 0 && q2 < 128 && q0 >= 0 && q0 < 128)
                np = (b == 0) ? q0 : q2;   // little-endian int64 [n0, n1]
            else
                np = (b == 0) ? q0 : q1;
        } else np = (b == 0) ? q0 : q1;
        out[n] = (p < np) ? atpm : 0.f;
    }
}

// ---------------------------------------------------------------------------
extern "C" void kernel_launch(void* const* d_in, const int* in_sizes, int n_in,
                              void* d_out, int out_size) {
    const float* x       = (const float*)d_in[0];
    const float* w_proj  = (const float*)d_in[1];
    const float* tower_w = (const float*)d_in[2];
    const float* tower_b = (const float*)d_in[3];
    const float* w_prof  = (const float*)d_in[4];
    const float* b_prof  = (const float*)d_in[5];
    const float* w_atpm  = (const float*)d_in[6];
    const float* b_atpm  = (const float*)d_in[7];
    const int*   n_peaks = (const int*)d_in[8];
    float* out = (float*)d_out;

    cudaFuncSetAttribute(conv_kernel,
                         cudaFuncAttributeMaxDynamicSharedMemorySize, CONV_SMEM);

    prep_kernel<<<(DEPTH * 16 * BSZ + 255) / 256, 256>>>(tower_w, w_proj);
    proj_kernel<<<dim3(LTOT / 128, HID / 128), 256>>>(x);
    for (int i = 0; i < DEPTH; i++)
        conv_kernel<<<dim3(LC / 128, NCHUNK), 256, CONV_SMEM>>>(
            i, 2 << i, i & 1, i == DEPTH - 1, tower_b + i * HID);
    heads_kernel<<<NCHUNK, 256>>>(w_prof, b_prof, w_atpm, b_atpm, n_peaks, out);
}

// round 9
// speedup vs baseline: 1.2015x; 1.1243x over previous
#include <cuda_runtime.h>
#include <math.h>
#include <stdint.h>

#define NCHUNK 256
#define LC 512
#define HID 256
#define MD 283
#define DEPTH 7
#define LTOT (NCHUNK * LC)

#define PITCH 136            // conv A pitch; 136 % 32 == 8 -> conflict-free frags
#define ASZ (48 * PITCH)     // 6528 words per conv A buffer
#define BSZ 12288            // words per B buffer (6 ks x 32 ntile x 32 lane x 2)
#define CONV_SMEM (2 * (ASZ + BSZ) * 4)   // 150528 bytes

#define P2 52                // proj A pitch; 52 % 32 == 20 -> conflict-free frags
#define A2SZ (128 * P2)      // 6656 words per proj A buffer
#define PROJ_SMEM (2 * (A2SZ + BSZ) * 4)  // 151552 bytes

// Ping-pong activation buffers [n][ch][pos]; intermediate layers hold
// tf32-rounded fp32 (so staging is a pure copy); final layer full fp32.
__device__ float g_bufA[NCHUNK * HID * LC];
__device__ float g_bufB[NCHUNK * HID * LC];
// Tower weights, m16n8k8 tf32 B-fragment layout:
// [layer][kc16(16)][kstep(6)][ntile(32)][lane(32)][reg(2)]
__device__ float g_wF2[DEPTH * 16 * BSZ];
// Proj weights, fragment layout: [kstep(36)][ntile(32)][lane(32)][reg(2)]
__device__ float g_wpF[36 * 2048];

// ---------------------------------------------------------------------------
// Weight prep
// ---------------------------------------------------------------------------
__global__ void prep_kernel(const float* __restrict__ tower_w,
                            const float* __restrict__ w_proj) {
    int i = blockIdx.x * blockDim.x + threadIdx.x;
    if (i < DEPTH * 16 * BSZ) {
        int local = i % BSZ;
        int blk = i / BSZ;
        int kc16 = blk & 15;
        int layer = blk >> 4;
        int reg = local & 1;
        int ln = (local >> 1) & 31;
        int nt = (local >> 6) & 31;
        int ks = local >> 11;               // 0..5
        int t = ks >> 1;
        int ic = kc16 * 16 + (ln & 3) + 4 * reg + 8 * (ks & 1);
        int oc = nt * 8 + (ln >> 2);
        float v = tower_w[(((layer * HID + oc) * HID) + ic) * 3 + t];
        unsigned tv; asm("cvt.rna.tf32.f32 %0, %1;" : "=r"(tv) : "f"(v));
        g_wF2[i] = __uint_as_float(tv);
    }
    if (i < 36 * 2048) {
        int reg = i & 1;
        int ln = (i >> 1) & 31;
        int nt = (i >> 6) & 31;
        int ks = i >> 11;                   // 0..35
        int h = nt * 8 + (ln >> 2);
        int m = ks * 8 + (ln & 3) + 4 * reg;
        float v = (m < MD) ? w_proj[h * MD + m] : 0.f;
        unsigned tv; asm("cvt.rna.tf32.f32 %0, %1;" : "=r"(tv) : "f"(v));
        g_wpF[i] = __uint_as_float(tv);
    }
}

// ---------------------------------------------------------------------------
// Projection via mma.sync tf32: D[pos][h] = sum_m x[pos][m] * w_proj[h][m].
// CTA 128 pos x 256 h, 512 threads (4m x 4n warps, warp tile 32x64).
// K=288 (padded), 6 chunks of 48; A staged [pos][k] pitch 52 via 4B cp.async
// (x rows are not 16B-aligned: MD=283).
// ---------------------------------------------------------------------------
__global__ __launch_bounds__(512, 1)
void proj_kernel(const float* __restrict__ x) {
    extern __shared__ float sm[];
    float* Ab[2] = {sm, sm + A2SZ};
    float* Bb[2] = {sm + 2 * A2SZ, sm + 2 * A2SZ + BSZ};
    uint32_t sbase = (uint32_t)__cvta_generic_to_shared(sm);
    uint32_t sAa[2] = {sbase, sbase + A2SZ * 4};
    uint32_t sBa[2] = {sbase + 2 * A2SZ * 4, sbase + (2 * A2SZ + BSZ) * 4};

    int m0 = blockIdx.x * 128;
    int tid = threadIdx.x;
    int lane = tid & 31;
    int warp = tid >> 5;
    int wm = warp & 3;
    int wn = warp >> 2;
    int tig = lane & 3;
    int grp = lane >> 2;

    float acc[2][8][4];
#pragma unroll
    for (int i = 0; i < 2; i++)
#pragma unroll
        for (int j = 0; j < 8; j++)
#pragma unroll
            for (int c = 0; c < 4; c++) acc[i][j][c] = 0.f;

    // stage chunk c: A = 128 pos x 48 k floats via 4B cp.async; B fragments 16B
    auto stage = [&](int c) {
        int kc = c * 48;
#pragma unroll
        for (int r = 0; r < 12; r++) {
            int idx = r * 512 + tid;        // 0..6143
            int pos = idx / 48;
            int k = idx - pos * 48;
            int gk = kc + k;
            int ok = (gk < MD) ? 4 : 0;
            const float* gs = x + (size_t)(m0 + pos) * MD + (ok ? gk : 0);
            asm volatile("cp.async.ca.shared.global [%0], [%1], 4, %2;"
                         :: "r"(sAa[c & 1] + (unsigned)(pos * P2 + k) * 4u),
                            "l"(__cvta_generic_to_global(gs)), "r"(ok));
        }
        const float* ws = g_wpF + (size_t)c * BSZ;
#pragma unroll
        for (int r = 0; r < 6; r++) {
            int idx = r * 512 + tid;
            asm volatile("cp.async.cg.shared.global [%0], [%1], 16, 16;"
                         :: "r"(sBa[c & 1] + (unsigned)idx * 16u),
                            "l"(__cvta_generic_to_global(ws + idx * 4)));
        }
        asm volatile("cp.async.commit_group;" ::: "memory");
    };

    stage(0);
    for (int c = 0; c < 6; c++) {
        if (c < 5) {
            stage(c + 1);
            asm volatile("cp.async.wait_group 1;" ::: "memory");
        } else {
            asm volatile("cp.async.wait_group 0;" ::: "memory");
        }
        __syncthreads();
        const float* Abuf = Ab[c & 1];
        const float* Bbuf = Bb[c & 1];
#pragma unroll
        for (int ks = 0; ks < 6; ks++) {
            unsigned a[2][4], b[8][2];
#pragma unroll
            for (int i = 0; i < 2; i++) {
                const float* ar = Abuf + (wm * 32 + i * 16 + grp) * P2 + ks * 8 + tig;
                a[i][0] = __float_as_uint(ar[0]);
                a[i][1] = __float_as_uint(ar[8 * P2]);
                a[i][2] = __float_as_uint(ar[4]);
                a[i][3] = __float_as_uint(ar[8 * P2 + 4]);
            }
#pragma unroll
            for (int j = 0; j < 8; j++) {
                uint2 bv = ((const uint2*)Bbuf)[(ks * 32 + wn * 8 + j) * 32 + lane];
                b[j][0] = bv.x; b[j][1] = bv.y;
            }
#pragma unroll
            for (int i = 0; i < 2; i++)
#pragma unroll
                for (int j = 0; j < 8; j++) {
                    asm volatile(
                        "mma.sync.aligned.m16n8k8.row.col.f32.tf32.tf32.f32 "
                        "{%0,%1,%2,%3}, {%4,%5,%6,%7}, {%8,%9}, {%0,%1,%2,%3};"
                        : "+f"(acc[i][j][0]), "+f"(acc[i][j][1]),
                          "+f"(acc[i][j][2]), "+f"(acc[i][j][3])
                        : "r"(a[i][0]), "r"(a[i][1]), "r"(a[i][2]), "r"(a[i][3]),
                          "r"(b[j][0]), "r"(b[j][1]));
                }
        }
        __syncthreads();
    }

    int n = m0 >> 9;
#pragma unroll
    for (int j = 0; j < 8; j++) {
        int h0 = wn * 64 + j * 8 + tig * 2;
#pragma unroll
        for (int i = 0; i < 2; i++) {
            int posb = (m0 & 511) + wm * 32 + i * 16 + grp;
#pragma unroll
            for (int cr = 0; cr < 4; cr++) {
                int pos = posb + ((cr & 2) ? 8 : 0);
                int h = h0 + (cr & 1);
                unsigned tv;
                asm("cvt.rna.tf32.f32 %0, %1;" : "=r"(tv) : "f"(acc[i][j][cr]));
                g_bufA[((size_t)n * HID + h) * LC + pos] = __uint_as_float(tv);
            }
        }
    }
}

// ---------------------------------------------------------------------------
// Stage one conv K-chunk (A: 8B pieces with tap shift + zfill; B: 16B copy).
// ---------------------------------------------------------------------------
__device__ __forceinline__ void stage_chunk(const float* __restrict__ inb,
                                            int layer, int kc16, int l0, int d,
                                            uint32_t sA, uint32_t sB, int tid) {
    int kc = kc16 * 16;
#pragma unroll
    for (int r = 0; r < 6; r++) {
        int idx = r * 512 + tid;        // 0..3071
        int row = idx >> 6;             // 0..47 : t*16 + kk
        int c8 = idx & 63;
        int tt = row >> 4;
        int gpos = l0 + c8 * 2 + (tt - 1) * d;
        int ok = ((unsigned)gpos < (unsigned)LC) ? 8 : 0;
        const float* gs = inb + (size_t)(kc + (row & 15)) * LC + (ok ? gpos : 0);
        asm volatile("cp.async.ca.shared.global [%0], [%1], 8, %2;"
                     :: "r"(sA + (unsigned)(row * PITCH + c8 * 2) * 4u),
                        "l"(__cvta_generic_to_global(gs)), "r"(ok));
    }
    const float* ws = g_wF2 + ((size_t)layer * 16 + kc16) * BSZ;
#pragma unroll
    for (int r = 0; r < 6; r++) {
        int idx = r * 512 + tid;
        asm volatile("cp.async.cg.shared.global [%0], [%1], 16, 16;"
                     :: "r"(sB + (unsigned)idx * 16u),
                        "l"(__cvta_generic_to_global(ws + idx * 4)));
    }
    asm volatile("cp.async.commit_group;" ::: "memory");
}

// ---------------------------------------------------------------------------
// Dilated conv layer via mma.sync tf32. CTA 128 pos x 256 oc, 512 threads
// (4m x 4n warps, warp tile 32 pos x 64 oc, 64 acc regs/thread, no spills).
// ---------------------------------------------------------------------------
__global__ __launch_bounds__(512, 1)
void conv_kernel(int layer, int d, int srcB, int last,
                 const float* __restrict__ bias) {
    extern __shared__ float sm[];
    float* Ab[2] = {sm, sm + ASZ};
    float* Bb[2] = {sm + 2 * ASZ, sm + 2 * ASZ + BSZ};
    uint32_t sbase = (uint32_t)__cvta_generic_to_shared(sm);
    uint32_t sAa[2] = {sbase, sbase + ASZ * 4};
    uint32_t sBa[2] = {sbase + 2 * ASZ * 4, sbase + (2 * ASZ + BSZ) * 4};

    const float* in = srcB ? g_bufB : g_bufA;
    float* out = srcB ? g_bufA : g_bufB;
    int l0 = blockIdx.x * 128;
    int n = blockIdx.y;

    int tid = threadIdx.x;
    int lane = tid & 31;
    int warp = tid >> 5;
    int wm = warp & 3;
    int wn = warp >> 2;
    int tig = lane & 3;
    int grp = lane >> 2;

    const float* inb = in + (size_t)n * HID * LC;

    float acc[2][8][4];
#pragma unroll
    for (int i = 0; i < 2; i++)
#pragma unroll
        for (int j = 0; j < 8; j++)
#pragma unroll
            for (int c = 0; c < 4; c++) acc[i][j][c] = 0.f;

    stage_chunk(inb, layer, 0, l0, d, sAa[0], sBa[0], tid);

    for (int c = 0; c < 16; c++) {
        if (c < 15) {
            stage_chunk(inb, layer, c + 1, l0, d, sAa[(c + 1) & 1],
                        sBa[(c + 1) & 1], tid);
            asm volatile("cp.async.wait_group 1;" ::: "memory");
        } else {
            asm volatile("cp.async.wait_group 0;" ::: "memory");
        }
        __syncthreads();
        const float* Abuf = Ab[c & 1];
        const float* Bbuf = Bb[c & 1];
#pragma unroll
        for (int ks = 0; ks < 6; ks++) {
            int rb = (ks >> 1) * 16 + (ks & 1) * 8;
            const float* ar0 = Abuf + (rb + tig) * PITCH + grp + wm * 32;
            const float* ar1 = Abuf + (rb + tig + 4) * PITCH + grp + wm * 32;
            unsigned a[2][4], b[8][2];
#pragma unroll
            for (int i = 0; i < 2; i++) {
                a[i][0] = __float_as_uint(ar0[i * 16]);
                a[i][1] = __float_as_uint(ar0[i * 16 + 8]);
                a[i][2] = __float_as_uint(ar1[i * 16]);
                a[i][3] = __float_as_uint(ar1[i * 16 + 8]);
            }
#pragma unroll
            for (int j = 0; j < 8; j++) {
                uint2 bv = ((const uint2*)Bbuf)[(ks * 32 + wn * 8 + j) * 32 + lane];
                b[j][0] = bv.x; b[j][1] = bv.y;
            }
#pragma unroll
            for (int i = 0; i < 2; i++)
#pragma unroll
                for (int j = 0; j < 8; j++) {
                    asm volatile(
                        "mma.sync.aligned.m16n8k8.row.col.f32.tf32.tf32.f32 "
                        "{%0,%1,%2,%3}, {%4,%5,%6,%7}, {%8,%9}, {%0,%1,%2,%3};"
                        : "+f"(acc[i][j][0]), "+f"(acc[i][j][1]),
                          "+f"(acc[i][j][2]), "+f"(acc[i][j][3])
                        : "r"(a[i][0]), "r"(a[i][1]), "r"(a[i][2]), "r"(a[i][3]),
                          "r"(b[j][0]), "r"(b[j][1]));
                }
        }
        __syncthreads();
    }

    // Epilogue: bias + gelu(c)+c; intermediate layers store tf32-rounded.
#pragma unroll
    for (int j = 0; j < 8; j++) {
        int oc0 = wn * 64 + j * 8 + tig * 2;
        float b0 = bias[oc0], b1 = bias[oc0 + 1];
#pragma unroll
        for (int i = 0; i < 2; i++) {
            int posb = l0 + wm * 32 + i * 16 + grp;
#pragma unroll
            for (int cr = 0; cr < 4; cr++) {
                int pos = posb + ((cr & 2) ? 8 : 0);
                int oc = oc0 + (cr & 1);
                float cc = acc[i][j][cr] + ((cr & 1) ? b1 : b0);
                float g = 0.5f * cc * (1.f + erff(cc * 0.70710678118654752f)) + cc;
                if (!last) {
                    unsigned tv;
                    asm("cvt.rna.tf32.f32 %0, %1;" : "=r"(tv) : "f"(g));
                    g = __uint_as_float(tv);
                }
                out[((size_t)n * HID + oc) * LC + pos] = g;
            }
        }
    }
}

// ---------------------------------------------------------------------------
// Heads: profile conv (K=20, pad 9/10) + mean-pool + atpm + mask.
// ---------------------------------------------------------------------------
__global__ __launch_bounds__(256)
void heads_kernel(const float* __restrict__ w_prof, const float* __restrict__ b_prof,
                  const float* __restrict__ w_atpm, const float* __restrict__ b_atpm,
                  const int* __restrict__ npq, float* __restrict__ out) {
    const float* in = g_bufB;   // DEPTH=7: final layer (i=6, srcB=0) wrote B
    int n = blockIdx.x;
    int tid = threadIdx.x;

    __shared__ float wp[HID * 20];
    __shared__ float wa[HID];
    __shared__ float row[LC];
    __shared__ float partial[256];

    for (int i = tid; i < HID * 20; i += 256) wp[i] = w_prof[i];
    wa[tid] = w_atpm[tid];

    float p0 = 0.f, p1 = 0.f, ap = 0.f;
    const float* base = in + (size_t)n * HID * LC;

    for (int ic = 0; ic < HID; ic++) {
        __syncthreads();
        row[tid] = base[ic * LC + tid];
        row[tid + 256] = base[ic * LC + tid + 256];
        __syncthreads();
        const float* wpr = &wp[ic * 20];
        float wv = wa[ic];
#pragma unroll
        for (int k = 0; k < 20; k++) {
            float w = wpr[k];
            int pos = tid + k - 9;
            if (pos >= 0 && pos < LC) p0 = fmaf(row[pos], w, p0);
            int pos2 = tid + 256 + k - 9;
            if (pos2 < LC) p1 = fmaf(row[pos2], w, p1);
        }
        ap = fmaf(wv, row[tid] + row[tid + 256], ap);
    }

    float bp = b_prof[0];
    out[256 + (size_t)n * LC + tid] = p0 + bp;
    out[256 + (size_t)n * LC + tid + 256] = p1 + bp;

    partial[tid] = ap;
    __syncthreads();
    for (int s = 128; s > 0; s >>= 1) {
        if (tid < s) partial[tid] += partial[tid + s];
        __syncthreads();
    }
    if (tid == 0) {
        float atpm = partial[0] * (1.f / 512.f) + b_atpm[0];
        int b = n >> 7, p = n & 127;
        int np;
        int q0 = npq[0], q1 = npq[1];
        if (q1 == 0) {
            int q2 = npq[2], q3 = npq[3];
            if (q3 == 0 && q2 >= 0 && q2 < 128 && q0 >= 0 && q0 < 128)
                np = (b == 0) ? q0 : q2;   // little-endian int64 [n0, n1]
            else
                np = (b == 0) ? q0 : q1;
        } else np = (b == 0) ? q0 : q1;
        out[n] = (p < np) ? atpm : 0.f;
    }
}

// ---------------------------------------------------------------------------
extern "C" void kernel_launch(void* const* d_in, const int* in_sizes, int n_in,
                              void* d_out, int out_size) {
    const float* x       = (const float*)d_in[0];
    const float* w_proj  = (const float*)d_in[1];
    const float* tower_w = (const float*)d_in[2];
    const float* tower_b = (const float*)d_in[3];
    const float* w_prof  = (const float*)d_in[4];
    const float* b_prof  = (const float*)d_in[5];
    const float* w_atpm  = (const float*)d_in[6];
    const float* b_atpm  = (const float*)d_in[7];
    const int*   n_peaks = (const int*)d_in[8];
    float* out = (float*)d_out;

    cudaFuncSetAttribute(conv_kernel,
                         cudaFuncAttributeMaxDynamicSharedMemorySize, CONV_SMEM);
    cudaFuncSetAttribute(proj_kernel,
                         cudaFuncAttributeMaxDynamicSharedMemorySize, PROJ_SMEM);

    prep_kernel<<<(DEPTH * 16 * BSZ + 255) / 256, 256>>>(tower_w, w_proj);
    proj_kernel<<<LTOT / 128, 512, PROJ_SMEM>>>(x);
    for (int i = 0; i < DEPTH; i++)
        conv_kernel<<<dim3(LC / 128, NCHUNK), 512, CONV_SMEM>>>(
            i, 2 << i, i & 1, i == DEPTH - 1, tower_b + i * HID);
    heads_kernel<<<NCHUNK, 256>>>(w_prof, b_prof, w_atpm, b_atpm, n_peaks, out);
}